// round 4
// baseline (speedup 1.0000x reference)
#include <cuda_runtime.h>
#include <cstdint>

// ============================================================================
// Problem constants
// ============================================================================
#define MDIM   65536      // B*N = 2048*32
#define KDIM   1024       // model dim
#define NQKV   3072       // 3*DIM
#define NPROJ  1024
#define HEADS  16
#define HEAD_D 64
#define SEQ    32
#define BATCH  2048

// Scratch (allocation-free rule: __device__ globals)
__device__ float g_qkv [(size_t)MDIM * NQKV];   // 805 MB
__device__ float g_attn[(size_t)MDIM * NPROJ];  // 268 MB

// ============================================================================
// Helpers — BASELINE PTX ONLY (compute_103 target: no tcgen05/TMEM/mbarrier)
// ============================================================================

// fp32 -> tf32 round-to-nearest-even (RNA). Unbiased: dot-product error stays
// ~2e-4 over K=1024. Truncation (what raw mma does to f32 bits) is one-sided
// and would accumulate to ~1e-2 — RNA here is correctness-critical.
__device__ __forceinline__ float f2tf32(float x) {
    uint32_t y;
    asm("cvt.rna.tf32.f32 %0, %1;" : "=r"(y) : "f"(x));
    return __uint_as_float(y);
}

// m16n8k8 tf32 HMMA (sm_80 baseline instruction, runs on the tensor pipe)
__device__ __forceinline__ void mma_tf32(float& c0, float& c1, float& c2, float& c3,
                                         uint32_t a0, uint32_t a1, uint32_t a2, uint32_t a3,
                                         uint32_t b0, uint32_t b1) {
    asm volatile(
        "mma.sync.aligned.m16n8k8.row.col.f32.tf32.tf32.f32 "
        "{%0,%1,%2,%3}, {%4,%5,%6,%7}, {%8,%9}, {%0,%1,%2,%3};"
        : "+f"(c0), "+f"(c1), "+f"(c2), "+f"(c3)
        : "r"(a0), "r"(a1), "r"(a2), "r"(a3), "r"(b0), "r"(b1));
}

// Bank swizzle for a [rows][32-float] tile: float index = row*32 + (k ^ ((row&7)<<2)).
// Makes both the producer STS.128 and all mma fragment LDS.32 patterns
// conflict-free (injective bank mapping over the 32 lanes).
__device__ __forceinline__ int swz_idx(int row, int k) {
    return row * 32 + (k ^ ((row & 7) << 2));
}

// ============================================================================
// GEMM: C[M,N] = A[M,K] @ W[N,K]^T + bias
//   tf32 mma.sync, CTA tile 128x128, BK=32, 8 warps (2x4), warp tile 64x32.
//   Double-buffered smem (64 KB), register prefetch hides DRAM latency.
// ============================================================================
static constexpr int SMEM_BYTES = 2 * (4096 + 4096) * 4;  // 2 stages * (A+B tiles)

__global__ void __launch_bounds__(256, 2)
gemm_tf32_kernel(const float* __restrict__ A, const float* __restrict__ W,
                 const float* __restrict__ bias, float* __restrict__ C,
                 int M, int N, int K)
{
    extern __shared__ float smem[];
    // float offsets: A0 [0,4096) A1 [4096,8192) B0 [8192,12288) B1 [12288,16384)

    const int tid  = threadIdx.x;
    const int lane = tid & 31;
    const int w    = tid >> 5;
    const int wm   = w >> 2;     // 0..1  (m direction, 64 rows each)
    const int wn   = w & 3;      // 0..3  (n direction, 32 cols each)

    // ---- grid swizzle: groups of 16 M-tiles, N-tile outer within group ----
    const int tiles_n = N >> 7;
    const int per = 16 * tiles_n;
    const int grp = blockIdx.x / per;
    const int r_  = blockIdx.x % per;
    const int m0  = (grp * 16 + (r_ % 16)) << 7;
    const int n0  = (r_ / 16) << 7;

    // ---- producer geometry: 8 threads per row (32 floats = 8 float4) ----
    const int prow = tid >> 3;        // 0..31, +32j for j=0..3
    const int k4   = (tid & 7) << 2;  // float4 column within the 32-wide k tile
    const int swsA = swz_idx(prow, k4);           // same row&7 for all j
    const float* Ab = A + (size_t)(m0 + prow) * K + k4;
    const float* Bb = W + (size_t)(n0 + prow) * K + k4;

    float4 ra[4], rb[4];
#pragma unroll
    for (int j = 0; j < 4; ++j) {
        ra[j] = *(const float4*)(Ab + (size_t)32 * j * K);
        rb[j] = *(const float4*)(Bb + (size_t)32 * j * K);
    }

    // cvt + store a staged tile into buffer s
    auto stage = [&](int s, const float4* xa, const float4* xb) {
        float* As = smem + s * 4096;
        float* Bs = smem + 8192 + s * 4096;
#pragma unroll
        for (int j = 0; j < 4; ++j) {
            float4 pa = make_float4(f2tf32(xa[j].x), f2tf32(xa[j].y),
                                    f2tf32(xa[j].z), f2tf32(xa[j].w));
            float4 pb = make_float4(f2tf32(xb[j].x), f2tf32(xb[j].y),
                                    f2tf32(xb[j].z), f2tf32(xb[j].w));
            *(float4*)(As + swsA + j * 1024) = pa;   // (+32 rows) * 32 floats
            *(float4*)(Bs + swsA + j * 1024) = pb;
        }
    };

    stage(0, ra, rb);
    __syncthreads();

    float acc[4][4][4];
#pragma unroll
    for (int mt = 0; mt < 4; ++mt)
#pragma unroll
        for (int nt = 0; nt < 4; ++nt)
#pragma unroll
            for (int i = 0; i < 4; ++i) acc[mt][nt][i] = 0.f;

    const int NK = K >> 5;  // 32 mainloop iterations
    const int lg = lane >> 2, lc = lane & 3;

#pragma unroll 1
    for (int kt = 0; kt < NK; ++kt) {
        const int s = kt & 1;
        // prefetch next tile into registers (overlaps with MMA below)
        if (kt + 1 < NK) {
#pragma unroll
            for (int j = 0; j < 4; ++j) {
                ra[j] = *(const float4*)(Ab + (size_t)(kt + 1) * 32 + (size_t)32 * j * K);
                rb[j] = *(const float4*)(Bb + (size_t)(kt + 1) * 32 + (size_t)32 * j * K);
            }
        }

        // ---- MMA over buffer s: 4 k-steps of 8 ----
        const float* As = smem + s * 4096;
        const float* Bs = smem + 8192 + s * 4096;
#pragma unroll
        for (int ks = 0; ks < 4; ++ks) {
            const int kk = ks * 8 + lc;
            uint32_t af[4][4], bf[4][2];
#pragma unroll
            for (int mt = 0; mt < 4; ++mt) {
                const int rr = wm * 64 + mt * 16 + lg;
                af[mt][0] = __float_as_uint(As[swz_idx(rr,     kk)]);
                af[mt][1] = __float_as_uint(As[swz_idx(rr + 8, kk)]);
                af[mt][2] = __float_as_uint(As[swz_idx(rr,     kk + 4)]);
                af[mt][3] = __float_as_uint(As[swz_idx(rr + 8, kk + 4)]);
            }
#pragma unroll
            for (int nt = 0; nt < 4; ++nt) {
                const int nn = wn * 32 + nt * 8 + lg;
                bf[nt][0] = __float_as_uint(Bs[swz_idx(nn, kk)]);
                bf[nt][1] = __float_as_uint(Bs[swz_idx(nn, kk + 4)]);
            }
#pragma unroll
            for (int mt = 0; mt < 4; ++mt)
#pragma unroll
                for (int nt = 0; nt < 4; ++nt)
                    mma_tf32(acc[mt][nt][0], acc[mt][nt][1], acc[mt][nt][2], acc[mt][nt][3],
                             af[mt][0], af[mt][1], af[mt][2], af[mt][3],
                             bf[nt][0], bf[nt][1]);
        }

        // ---- stage next tile into the other buffer ----
        if (kt + 1 < NK) {
            stage(s ^ 1, ra, rb);
        }
        __syncthreads();
    }

    // ---- epilogue: direct float2 global stores with bias ----
#pragma unroll
    for (int nt = 0; nt < 4; ++nt) {
        const int col = n0 + wn * 32 + nt * 8 + 2 * lc;
        const float b0 = __ldg(bias + col), b1 = __ldg(bias + col + 1);
#pragma unroll
        for (int mt = 0; mt < 4; ++mt) {
            const int row = m0 + wm * 64 + mt * 16 + lg;
            float2 v0 = make_float2(acc[mt][nt][0] + b0, acc[mt][nt][1] + b1);
            float2 v1 = make_float2(acc[mt][nt][2] + b0, acc[mt][nt][3] + b1);
            *(float2*)(C + (size_t)row * N + col)       = v0;
            *(float2*)(C + (size_t)(row + 8) * N + col) = v1;
        }
    }
}

// ============================================================================
// Attention: per (b,h): s = q k^T * 0.125 + rel_bias[h]; p = softmax(s); o = p v
// ============================================================================
__global__ void __launch_bounds__(128)
attn_kernel(const float* __restrict__ qkv, const float* __restrict__ rel_bias,
            float* __restrict__ attn_out)
{
    __shared__ float q[32][65], k[32][65], v[32][65], s[32][33];
    const int bh = blockIdx.x;
    const int b = bh >> 4, h = bh & 15;
    const int tid = threadIdx.x;

    const size_t base = (size_t)b * SEQ * NQKV + (size_t)h * HEAD_D;
    for (int i = tid; i < SEQ * HEAD_D; i += 128) {
        int n = i >> 6, d = i & 63;
        size_t a = base + (size_t)n * NQKV + d;
        q[n][d] = qkv[a];
        k[n][d] = qkv[a + 1024];
        v[n][d] = qkv[a + 2048];
    }
    __syncthreads();

    // scores: thread -> n = tid/4, m = (tid%4) + 4j
    {
        const int n  = tid >> 2;
        const int mb = tid & 3;
        const float* rbp = rel_bias + ((size_t)h * 32 + n) * 32;
#pragma unroll
        for (int j = 0; j < 8; ++j) {
            int m = mb + 4 * j;
            float acc = 0.f;
#pragma unroll
            for (int d = 0; d < 64; ++d) acc += q[n][d] * k[m][d];
            s[n][m] = acc * 0.125f + rbp[m];
        }
    }
    __syncthreads();

    // softmax rows: warp w handles rows [8w, 8w+8), lane = column
    {
        const int lane = tid & 31, w = tid >> 5;
        for (int rr = w * 8; rr < w * 8 + 8; ++rr) {
            float x = s[rr][lane];
            float mx = x;
#pragma unroll
            for (int off = 16; off > 0; off >>= 1)
                mx = fmaxf(mx, __shfl_xor_sync(0xFFFFFFFFu, mx, off));
            float e = __expf(x - mx);
            float sum = e;
#pragma unroll
            for (int off = 16; off > 0; off >>= 1)
                sum += __shfl_xor_sync(0xFFFFFFFFu, sum, off);
            s[rr][lane] = e / sum;
        }
    }
    __syncthreads();

    // out = p @ v -> [B,N,H*D] layout for the proj GEMM
    for (int i = tid; i < SEQ * HEAD_D; i += 128) {
        int n = i >> 6, d = i & 63;
        float acc = 0.f;
#pragma unroll
        for (int m = 0; m < 32; ++m) acc += s[n][m] * v[m][d];
        attn_out[((size_t)b * SEQ + n) * NPROJ + (size_t)h * HEAD_D + d] = acc;
    }
}

// ============================================================================
// Launcher
// ============================================================================
extern "C" void kernel_launch(void* const* d_in, const int* in_sizes, int n_in,
                              void* d_out, int out_size)
{
    const float* x      = (const float*)d_in[0];
    const float* W_qkv  = (const float*)d_in[1];
    const float* b_qkv  = (const float*)d_in[2];
    const float* W_proj = (const float*)d_in[3];
    const float* b_proj = (const float*)d_in[4];
    const float* rbias  = (const float*)d_in[5];
    float* out = (float*)d_out;

    void *p_qkv = nullptr, *p_attn = nullptr;
    cudaGetSymbolAddress(&p_qkv, g_qkv);
    cudaGetSymbolAddress(&p_attn, g_attn);

    cudaFuncSetAttribute(gemm_tf32_kernel,
                         cudaFuncAttributeMaxDynamicSharedMemorySize, SMEM_BYTES);

    // GEMM1: qkv = x @ W_qkv^T + b_qkv  [65536 x 3072]
    gemm_tf32_kernel<<<(MDIM / 128) * (NQKV / 128), 256, SMEM_BYTES>>>(
        x, W_qkv, b_qkv, (float*)p_qkv, MDIM, NQKV, KDIM);

    // Attention: 2048*16 (b,h) blocks
    attn_kernel<<<BATCH * HEADS, 128>>>((const float*)p_qkv, rbias, (float*)p_attn);

    // GEMM2: out = attn @ W_proj^T + b_proj  [65536 x 1024]
    gemm_tf32_kernel<<<(MDIM / 128) * (NPROJ / 128), 256, SMEM_BYTES>>>(
        (const float*)p_attn, W_proj, b_proj, out, MDIM, NPROJ, KDIM);
}